// round 2
// baseline (speedup 1.0000x reference)
#include <cuda_runtime.h>
#include <math.h>

// Problem constants (fixed shapes)
#define SS 2048
#define BB 32
#define HH 1024
#define RR (SS*BB)   // 65536 flattened (s,b) rows

// Scratch (device globals: no allocation allowed)
static __device__ float g_c[BB*HH];       // c[b,k] = W2 h[b] + b1 + b2
static __device__ float g_energy[RR];     // energy[s*B+b]
static __device__ float g_attn[RR];       // softmax weights
static __device__ int   g_mask_kind;      // 0=uint8/bool, 1=int32, 2=float32

// ---------------------------------------------------------------------------
// Mask dtype detection: sample first 4096 bytes (in-bounds for every layout).
// bool/uint8 Bernoulli(0.5): nonzero bytes at all (i mod 4) offsets.
// int32 0/1 little-endian:   nonzero only at offset 0.
// float32 0.0/1.0f:          nonzero only at offsets 2,3 (0x3F80...).
// ---------------------------------------------------------------------------
__global__ void detect_mask_kernel(const unsigned char* __restrict__ m) {
    __shared__ int nz0, nz3;
    if (threadIdx.x == 0) { nz0 = 0; nz3 = 0; }
    __syncthreads();
    int l0 = 0, l3 = 0;
    int base = threadIdx.x * 16;
    #pragma unroll
    for (int j = 0; j < 16; j++) {
        int i = base + j;
        unsigned char v = m[i];
        if (v) {
            if ((i & 3) == 0) l0++;
            if ((i & 3) == 3) l3++;
        }
    }
    if (l0) atomicAdd(&nz0, l0);
    if (l3) atomicAdd(&nz3, l3);
    __syncthreads();
    if (threadIdx.x == 0) {
        int kind;
        if (nz0 > 0 && nz3 > 0)      kind = 0;  // bool bytes
        else if (nz0 > 0)            kind = 1;  // int32
        else                         kind = 2;  // float32
        g_mask_kind = kind;
    }
}

__device__ __forceinline__ bool mask_on(const void* m, int idx, int kind) {
    if (kind == 0) return ((const unsigned char*)m)[idx] != 0;
    if (kind == 1) return ((const int*)m)[idx] != 0;
    return ((const float*)m)[idx] != 0.0f;
}

// ---------------------------------------------------------------------------
// Accurate-enough tanh (safe under --use_fast_math; tanhf would degrade there)
// ---------------------------------------------------------------------------
__device__ __forceinline__ float my_tanh(float x) {
    float xc = fminf(fmaxf(x, -15.f), 15.f);
    float e  = __expf(2.f * xc);
    return __fdividef(e - 1.f, e + 1.f);
}

// ---------------------------------------------------------------------------
// Kernel A: c[b,k] = b1[k] + b2[k] + sum_h hidden[b,h] * W2[k,h]
// 32 blocks (one per b), 256 threads
// ---------------------------------------------------------------------------
__global__ void precompute_c_kernel(const float* __restrict__ hidden,
                                    const float* __restrict__ W2,
                                    const float* __restrict__ b1,
                                    const float* __restrict__ b2) {
    __shared__ __align__(16) float hv[HH];
    int b = blockIdx.x;
    for (int h = threadIdx.x; h < HH; h += blockDim.x)
        hv[h] = hidden[b*HH + h];
    __syncthreads();
    for (int k = threadIdx.x; k < HH; k += blockDim.x) {
        const float4* w = (const float4*)(W2 + k*HH);
        const float4* hh4 = (const float4*)hv;
        float acc = 0.f;
        #pragma unroll 8
        for (int q = 0; q < HH/4; q++) {
            float4 wv = w[q];
            float4 hh = hh4[q];
            acc += wv.x*hh.x + wv.y*hh.y + wv.z*hh.z + wv.w*hh.w;
        }
        g_c[b*HH + k] = acc + b1[k] + b2[k];
    }
}

__global__ void zero_energy_kernel() {
    int i = blockIdx.x * blockDim.x + threadIdx.x;
    if (i < RR) g_energy[i] = 0.f;
}

__global__ void zero_out_kernel(float* __restrict__ out) {
    int i = blockIdx.x * blockDim.x + threadIdx.x;
    if (i < BB*HH) out[i] = 0.f;
}

// ---------------------------------------------------------------------------
// Kernel B: the big fused GEMM.
//   pre[r,k] = sum_h A[r,h]*W1[k,h] + c[r%32, k]
//   energy[r] += sum_k tanh(pre[r,k]) * v[k]      (atomic partial per N-tile)
// Tile: BM=128 rows x BN=128 cols, BK=16 depth, 256 threads, 8x8 microtile.
// Grid: (RR/128, HH/128) = (512, 8)
// ---------------------------------------------------------------------------
#define BM 128
#define BN 128
#define BK 16

__global__ __launch_bounds__(256)
void energy_gemm_kernel(const float* __restrict__ A,    // (RR, HH)
                        const float* __restrict__ W1,   // (HH, HH), row k
                        const float* __restrict__ v) {
    __shared__ __align__(16) float As[BK][BM];
    __shared__ __align__(16) float Bs[BK][BN];

    const int m0  = blockIdx.x * BM;
    const int n0  = blockIdx.y * BN;
    const int tid = threadIdx.x;
    const int tx  = tid & 15;     // 0..15 -> 8 cols each
    const int ty  = tid >> 4;     // 0..15 -> 8 rows each

    const int lrow = tid >> 1;         // 0..127
    const int lcol = (tid & 1) * 8;    // 0 or 8

    const float* Aptr = A  + (m0 + lrow)*HH + lcol;
    const float* Bptr = W1 + (n0 + lrow)*HH + lcol;

    float acc[8][8];
    #pragma unroll
    for (int i = 0; i < 8; i++)
        #pragma unroll
        for (int j = 0; j < 8; j++) acc[i][j] = 0.f;

    for (int k0 = 0; k0 < HH; k0 += BK) {
        float4 a0 = *(const float4*)(Aptr + k0);
        float4 a1 = *(const float4*)(Aptr + k0 + 4);
        float4 w0 = *(const float4*)(Bptr + k0);
        float4 w1 = *(const float4*)(Bptr + k0 + 4);

        __syncthreads();   // previous iteration's reads complete
        As[lcol+0][lrow] = a0.x; As[lcol+1][lrow] = a0.y;
        As[lcol+2][lrow] = a0.z; As[lcol+3][lrow] = a0.w;
        As[lcol+4][lrow] = a1.x; As[lcol+5][lrow] = a1.y;
        As[lcol+6][lrow] = a1.z; As[lcol+7][lrow] = a1.w;
        Bs[lcol+0][lrow] = w0.x; Bs[lcol+1][lrow] = w0.y;
        Bs[lcol+2][lrow] = w0.z; Bs[lcol+3][lrow] = w0.w;
        Bs[lcol+4][lrow] = w1.x; Bs[lcol+5][lrow] = w1.y;
        Bs[lcol+6][lrow] = w1.z; Bs[lcol+7][lrow] = w1.w;
        __syncthreads();   // stores visible

        #pragma unroll
        for (int kk = 0; kk < BK; kk++) {
            float4 ta = *(const float4*)&As[kk][ty*8];
            float4 tb = *(const float4*)&As[kk][ty*8 + 4];
            float4 ua = *(const float4*)&Bs[kk][tx*8];
            float4 ub = *(const float4*)&Bs[kk][tx*8 + 4];
            float ar[8] = {ta.x, ta.y, ta.z, ta.w, tb.x, tb.y, tb.z, tb.w};
            float br[8] = {ua.x, ua.y, ua.z, ua.w, ub.x, ub.y, ub.z, ub.w};
            #pragma unroll
            for (int i = 0; i < 8; i++)
                #pragma unroll
                for (int j = 0; j < 8; j++)
                    acc[i][j] += ar[i] * br[j];
        }
    }

    // Epilogue: + c[b,k], tanh, * v[k], row-reduce, atomic partial energy
    float vv[8];
    #pragma unroll
    for (int j = 0; j < 8; j++) vv[j] = v[n0 + tx*8 + j];

    float p[8];
    #pragma unroll
    for (int i = 0; i < 8; i++) {
        int r = m0 + ty*8 + i;
        const float* crow = g_c + (r & (BB-1))*HH + n0 + tx*8;
        float s = 0.f;
        #pragma unroll
        for (int j = 0; j < 8; j++)
            s += my_tanh(acc[i][j] + crow[j]) * vv[j];
        p[i] = s;
    }

    // reduce across the 16 tx lanes (lanes with same ty parity stay in-warp)
    #pragma unroll
    for (int off = 1; off < 16; off <<= 1)
        #pragma unroll
        for (int i = 0; i < 8; i++)
            p[i] += __shfl_xor_sync(0xffffffffu, p[i], off);

    if (tx == 0) {
        #pragma unroll
        for (int i = 0; i < 8; i++)
            atomicAdd(&g_energy[m0 + ty*8 + i], p[i]);
    }
}

// ---------------------------------------------------------------------------
// Kernel C1: masked softmax over S per batch b. 32 blocks x 256 threads.
// ---------------------------------------------------------------------------
__global__ void softmax_kernel(const void* __restrict__ mask) {
    const int b = blockIdx.x;
    const int kind = g_mask_kind;
    __shared__ float red[256];

    float lmax = -3.4e38f;
    for (int s = threadIdx.x; s < SS; s += 256) {
        int idx = s*BB + b;
        float e = mask_on(mask, idx, kind) ? g_energy[idx] : -1e10f;
        g_energy[idx] = e;            // same-thread write/read mapping
        lmax = fmaxf(lmax, e);
    }
    red[threadIdx.x] = lmax;
    __syncthreads();
    for (int o = 128; o > 0; o >>= 1) {
        if (threadIdx.x < o) red[threadIdx.x] = fmaxf(red[threadIdx.x], red[threadIdx.x + o]);
        __syncthreads();
    }
    const float mx = red[0];
    __syncthreads();

    float lsum = 0.f;
    for (int s = threadIdx.x; s < SS; s += 256) {
        int idx = s*BB + b;
        float e = __expf(g_energy[idx] - mx);
        g_attn[idx] = e;
        lsum += e;
    }
    red[threadIdx.x] = lsum;
    __syncthreads();
    for (int o = 128; o > 0; o >>= 1) {
        if (threadIdx.x < o) red[threadIdx.x] += red[threadIdx.x + o];
        __syncthreads();
    }
    const float inv = 1.f / red[0];
    __syncthreads();

    for (int s = threadIdx.x; s < SS; s += 256)
        g_attn[s*BB + b] *= inv;
}

// ---------------------------------------------------------------------------
// Kernel C2: context[b,h] = sum_s attn[s,b]*hs[s,b,h]. Split-S with atomics.
// Grid (B, 16 s-chunks of 128), 256 threads; thread owns 4 contiguous h.
// ---------------------------------------------------------------------------
__global__ void context_kernel(const float* __restrict__ hs,
                               float* __restrict__ out) {
    const int b = blockIdx.x;
    const int s0 = blockIdx.y * 128;
    const int h4 = threadIdx.x;     // h = h4*4
    float4 acc = make_float4(0.f, 0.f, 0.f, 0.f);
    for (int s = s0; s < s0 + 128; s++) {
        float w = g_attn[s*BB + b];
        float4 x = ((const float4*)(hs + (size_t)(s*BB + b)*HH))[h4];
        acc.x += w*x.x; acc.y += w*x.y; acc.z += w*x.z; acc.w += w*x.w;
    }
    float* o = out + b*HH + h4*4;
    atomicAdd(o+0, acc.x); atomicAdd(o+1, acc.y);
    atomicAdd(o+2, acc.z); atomicAdd(o+3, acc.w);
}

// ---------------------------------------------------------------------------
// Launch
// Inputs: 0 hidden (1,B,H) | 1 hidden_sequence (S,B,H) | 2 input_masks (S,B)
//         3 W1 (H,H) | 4 b1 (H) | 5 W2 (H,H) | 6 b2 (H) | 7 v (H)
// Output: context (1,B,H) float32
// ---------------------------------------------------------------------------
extern "C" void kernel_launch(void* const* d_in, const int* in_sizes, int n_in,
                              void* d_out, int out_size) {
    const float* hidden = (const float*)d_in[0];
    const float* hs     = (const float*)d_in[1];
    const void*  mask   = d_in[2];
    const float* W1     = (const float*)d_in[3];
    const float* b1     = (const float*)d_in[4];
    const float* W2     = (const float*)d_in[5];
    const float* b2     = (const float*)d_in[6];
    const float* v      = (const float*)d_in[7];
    float* out = (float*)d_out;

    detect_mask_kernel<<<1, 256>>>((const unsigned char*)mask);
    precompute_c_kernel<<<BB, 256>>>(hidden, W2, b1, b2);
    zero_energy_kernel<<<RR/256, 256>>>();
    energy_gemm_kernel<<<dim3(RR/BM, HH/BN), 256>>>(hs, W1, v);
    softmax_kernel<<<BB, 256>>>(mask);
    zero_out_kernel<<<(BB*HH)/256, 256>>>(out);
    context_kernel<<<dim3(BB, SS/128), 256>>>(hs, out);
}

// round 4
// speedup vs baseline: 2.1259x; 2.1259x over previous
#include <cuda_runtime.h>
#include <cuda_bf16.h>
#include <stdint.h>
#include <math.h>

#define SS 2048
#define BB 32
#define HH 1024
#define RR (SS*BB)

// ---------------- device scratch (no allocation allowed) ----------------
static __device__ float g_c[BB*HH];
static __device__ float g_energy[RR];
static __device__ float g_attn[RR];
static __device__ int   g_mask_kind;
static __device__ __align__(16) __nv_bfloat16 g_Whi[HH*HH];
static __device__ __align__(16) __nv_bfloat16 g_Wlo[HH*HH];

// ---------------- helpers ----------------
__device__ __forceinline__ uint32_t smem_u32(const void* p) {
    uint32_t a;
    asm("{ .reg .u64 t; cvta.to.shared.u64 t, %1; cvt.u32.u64 %0, t; }" : "=r"(a) : "l"(p));
    return a;
}
__device__ __forceinline__ uint32_t cvt2bf(float hi, float lo) {
    uint32_t r;
    asm("cvt.rn.bf16x2.f32 %0, %1, %2;" : "=r"(r) : "f"(hi), "f"(lo));
    return r;
}
__device__ __forceinline__ float bflo_f(uint32_t w) { return __uint_as_float(w << 16); }
__device__ __forceinline__ float bfhi_f(uint32_t w) { return __uint_as_float(w & 0xffff0000u); }

__device__ __forceinline__ float my_tanh(float x) {
    float xc = fminf(fmaxf(x, -15.f), 15.f);
    float e  = __expf(2.f * xc);
    return __fdividef(e - 1.f, e + 1.f);
}

__device__ __forceinline__ void ldm4(uint32_t* r, uint32_t addr) {
    asm volatile("ldmatrix.sync.aligned.m8n8.x4.shared.b16 {%0,%1,%2,%3}, [%4];"
        : "=r"(r[0]), "=r"(r[1]), "=r"(r[2]), "=r"(r[3]) : "r"(addr));
}
__device__ __forceinline__ void mma16816(float* d, const uint32_t* a, const uint32_t* b) {
    asm volatile("mma.sync.aligned.m16n8k16.row.col.f32.bf16.bf16.f32 "
        "{%0,%1,%2,%3}, {%4,%5,%6,%7}, {%8,%9}, {%0,%1,%2,%3};"
        : "+f"(d[0]), "+f"(d[1]), "+f"(d[2]), "+f"(d[3])
        : "r"(a[0]), "r"(a[1]), "r"(a[2]), "r"(a[3]), "r"(b[0]), "r"(b[1]));
}
#define CP_ASYNC16(dst, src) \
    asm volatile("cp.async.cg.shared.global [%0], [%1], 16;" :: "r"(dst), "l"(src) : "memory")
#define CP_COMMIT()  asm volatile("cp.async.commit_group;" ::: "memory")
#define CP_WAIT0()   asm volatile("cp.async.wait_group 0;" ::: "memory")

// ---------------------------------------------------------------------------
// Mask dtype detection
// ---------------------------------------------------------------------------
__global__ void detect_mask_kernel(const unsigned char* __restrict__ m) {
    __shared__ int nz0, nz3;
    if (threadIdx.x == 0) { nz0 = 0; nz3 = 0; }
    __syncthreads();
    int l0 = 0, l3 = 0;
    int base = threadIdx.x * 16;
    #pragma unroll
    for (int j = 0; j < 16; j++) {
        int i = base + j;
        unsigned char v = m[i];
        if (v) { if ((i & 3) == 0) l0++; if ((i & 3) == 3) l3++; }
    }
    if (l0) atomicAdd(&nz0, l0);
    if (l3) atomicAdd(&nz3, l3);
    __syncthreads();
    if (threadIdx.x == 0) {
        int kind;
        if (nz0 > 0 && nz3 > 0) kind = 0;
        else if (nz0 > 0)       kind = 1;
        else                    kind = 2;
        g_mask_kind = kind;
    }
}
__device__ __forceinline__ bool mask_on(const void* m, int idx, int kind) {
    if (kind == 0) return ((const unsigned char*)m)[idx] != 0;
    if (kind == 1) return ((const int*)m)[idx] != 0;
    return ((const float*)m)[idx] != 0.0f;
}

// ---------------------------------------------------------------------------
// W1 -> bf16 hi/lo planes
// ---------------------------------------------------------------------------
__global__ void convert_w_kernel(const float* __restrict__ W1) {
    int i = (blockIdx.x * 256 + threadIdx.x) * 4;
    float4 x = *(const float4*)(W1 + i);
    uint32_t h0 = cvt2bf(x.y, x.x), h1 = cvt2bf(x.w, x.z);
    uint32_t l0 = cvt2bf(x.y - bfhi_f(h0), x.x - bflo_f(h0));
    uint32_t l1 = cvt2bf(x.w - bfhi_f(h1), x.z - bflo_f(h1));
    *(uint2*)((char*)g_Whi + (size_t)i * 2) = make_uint2(h0, h1);
    *(uint2*)((char*)g_Wlo + (size_t)i * 2) = make_uint2(l0, l1);
}

// ---------------------------------------------------------------------------
// c[b,k] = b1[k] + b2[k] + sum_h hidden[b,h] * W2[k,h]
// ---------------------------------------------------------------------------
__global__ void precompute_c_kernel(const float* __restrict__ hidden,
                                    const float* __restrict__ W2,
                                    const float* __restrict__ b1,
                                    const float* __restrict__ b2) {
    __shared__ __align__(16) float hv[HH];
    int b = blockIdx.x;
    for (int h = threadIdx.x; h < HH; h += blockDim.x)
        hv[h] = hidden[b*HH + h];
    __syncthreads();
    for (int k = threadIdx.x; k < HH; k += blockDim.x) {
        const float4* w = (const float4*)(W2 + (size_t)k*HH);
        const float4* hh4 = (const float4*)hv;
        float acc = 0.f;
        #pragma unroll 8
        for (int q = 0; q < HH/4; q++) {
            float4 wv = w[q]; float4 hh = hh4[q];
            acc += wv.x*hh.x + wv.y*hh.y + wv.z*hh.z + wv.w*hh.w;
        }
        g_c[b*HH + k] = acc + b1[k] + b2[k];
    }
}

__global__ void zero_energy_kernel() {
    int i = blockIdx.x * blockDim.x + threadIdx.x;
    if (i < RR) g_energy[i] = 0.f;
}
__global__ void zero_out_kernel(float* __restrict__ out) {
    int i = blockIdx.x * blockDim.x + threadIdx.x;
    if (i < BB*HH) out[i] = 0.f;
}

// ---------------------------------------------------------------------------
// HMMA energy GEMM.
//   CTA tile M=128 x N=128, BK=32, 256 threads (2x4 warps, warp tile 64x32).
//   D += Ah*Wh + Ah*Wl + Al*Wh   (bf16 2-term split, fp32 reg accum)
//   Epilogue: pre = D + c[b,k]; energy += tanh(pre)*v[k]  (atomic)
// SMEM: double-buffered {A_hi, A_lo, W_hi, W_lo}, 128 rows x 32 cols bf16,
//       row stride padded to 80B (conflict-free ldmatrix).
// ---------------------------------------------------------------------------
#define PADB   80
#define OFF_AL 10240
#define OFF_WH 20480
#define OFF_WL 30720
#define STAGE  40960
#define DSMEM_TOTAL (2*STAGE)     // 81920

__global__ __launch_bounds__(256, 1)
void energy_mma_kernel(const float* __restrict__ A,   // (RR, HH)
                       const float* __restrict__ v) {
    extern __shared__ __align__(128) char smem[];
    const uint32_t sb = smem_u32(smem);
    const int tid = threadIdx.x, lane = tid & 31, wid = tid >> 5;
    const int wy = wid & 1, wx = wid >> 1;           // warp grid 2(M) x 4(N)
    const int n0 = blockIdx.x * 128;                 // n-block FAST -> L2 reuse of A
    const int m0 = blockIdx.y * 128;

    // ---- per-thread load mappings ----
    // A: thread covers 16 floats: row = tid>>1, half = tid&1
    const int arow = tid >> 1, ahalf = tid & 1;
    const float* Ag = A + (size_t)(m0 + arow) * HH + ahalf * 16;
    const uint32_t sA = sb + arow * PADB + ahalf * 32;
    // W: 4 x 16B cp.async per thread
    uint32_t wdst[4]; const __nv_bfloat16* wsrc[4];
    #pragma unroll
    for (int i = 0; i < 4; i++) {
        int plane = i >> 1;
        int s = tid + (i & 1) * 256;        // 0..511
        int row = s >> 2, q = s & 3;
        wsrc[i] = (plane ? g_Wlo : g_Whi) + (size_t)(n0 + row) * HH + q * 8;
        wdst[i] = sb + (plane ? OFF_WL : OFF_WH) + row * PADB + q * 16;
    }

    float acc[4][4][4];
    #pragma unroll
    for (int a = 0; a < 4; a++)
        #pragma unroll
        for (int b = 0; b < 4; b++)
            #pragma unroll
            for (int cReg = 0; cReg < 4; cReg++) acc[a][b][cReg] = 0.f;

    // ldmatrix base addresses (per-lane, stage-relative)
    const uint32_t aAbase = (wy * 64 + (lane & 15)) * PADB + (lane >> 4) * 16;
    const uint32_t aBbase = (wx * 32 + (lane & 7) + ((lane >> 4) << 3)) * PADB
                          + ((lane >> 3) & 1) * 16;

    // ---- prologue: stage chunk 0 into buffer 0 ----
    {
        #pragma unroll
        for (int i = 0; i < 4; i++) CP_ASYNC16(wdst[i], wsrc[i]);
        CP_COMMIT();
        float4 x0 = *(const float4*)(Ag + 0);
        float4 x1 = *(const float4*)(Ag + 4);
        float4 x2 = *(const float4*)(Ag + 8);
        float4 x3 = *(const float4*)(Ag + 12);
        uint32_t h0 = cvt2bf(x0.y, x0.x), h1 = cvt2bf(x0.w, x0.z);
        uint32_t h2 = cvt2bf(x1.y, x1.x), h3 = cvt2bf(x1.w, x1.z);
        uint32_t h4 = cvt2bf(x2.y, x2.x), h5 = cvt2bf(x2.w, x2.z);
        uint32_t h6 = cvt2bf(x3.y, x3.x), h7 = cvt2bf(x3.w, x3.z);
        *(uint4*)(smem + (sA - sb))      = make_uint4(h0, h1, h2, h3);
        *(uint4*)(smem + (sA - sb) + 16) = make_uint4(h4, h5, h6, h7);
        uint32_t l0 = cvt2bf(x0.y - bfhi_f(h0), x0.x - bflo_f(h0));
        uint32_t l1 = cvt2bf(x0.w - bfhi_f(h1), x0.z - bflo_f(h1));
        uint32_t l2 = cvt2bf(x1.y - bfhi_f(h2), x1.x - bflo_f(h2));
        uint32_t l3 = cvt2bf(x1.w - bfhi_f(h3), x1.z - bflo_f(h3));
        uint32_t l4 = cvt2bf(x2.y - bfhi_f(h4), x2.x - bflo_f(h4));
        uint32_t l5 = cvt2bf(x2.w - bfhi_f(h5), x2.z - bflo_f(h5));
        uint32_t l6 = cvt2bf(x3.y - bfhi_f(h6), x3.x - bflo_f(h6));
        uint32_t l7 = cvt2bf(x3.w - bfhi_f(h7), x3.z - bflo_f(h7));
        *(uint4*)(smem + (sA - sb) + OFF_AL)      = make_uint4(l0, l1, l2, l3);
        *(uint4*)(smem + (sA - sb) + OFF_AL + 16) = make_uint4(l4, l5, l6, l7);
        CP_WAIT0();
        __syncthreads();
    }

    // ---- main loop over 32 K-chunks ----
    for (int c = 0; c < HH/32; c++) {
        const int bf = c & 1;
        const uint32_t st = bf * STAGE;
        float4 x0, x1, x2, x3;
        if (c < HH/32 - 1) {
            const uint32_t nst = (1 - bf) * STAGE;
            #pragma unroll
            for (int i = 0; i < 4; i++)
                CP_ASYNC16(wdst[i] + nst, wsrc[i] + (c + 1) * 32);
            CP_COMMIT();
            const float* g = Ag + (c + 1) * 32;
            x0 = *(const float4*)(g + 0);
            x1 = *(const float4*)(g + 4);
            x2 = *(const float4*)(g + 8);
            x3 = *(const float4*)(g + 12);
        }

        // compute current chunk
        #pragma unroll
        for (int ks = 0; ks < 2; ks++) {
            uint32_t ah[4][4], al[4][4], bh[4][2], bl[4][2];
            const uint32_t kb = ks * 32;
            #pragma unroll
            for (int mi = 0; mi < 4; mi++) {
                uint32_t ad = sb + st + aAbase + mi * (16 * PADB) + kb;
                ldm4(ah[mi], ad);
                ldm4(al[mi], ad + OFF_AL);
            }
            #pragma unroll
            for (int nh = 0; nh < 2; nh++) {
                uint32_t t[4];
                uint32_t bd = sb + st + OFF_WH + aBbase + nh * (16 * PADB) + kb;
                ldm4(t, bd);
                bh[2*nh][0] = t[0]; bh[2*nh][1] = t[1];
                bh[2*nh+1][0] = t[2]; bh[2*nh+1][1] = t[3];
                ldm4(t, bd + (OFF_WL - OFF_WH));
                bl[2*nh][0] = t[0]; bl[2*nh][1] = t[1];
                bl[2*nh+1][0] = t[2]; bl[2*nh+1][1] = t[3];
            }
            #pragma unroll
            for (int mi = 0; mi < 4; mi++)
                #pragma unroll
                for (int nj = 0; nj < 4; nj++) {
                    mma16816(acc[mi][nj], ah[mi], bh[nj]);
                    mma16816(acc[mi][nj], ah[mi], bl[nj]);
                    mma16816(acc[mi][nj], al[mi], bh[nj]);
                }
        }

        if (c < HH/32 - 1) {
            const uint32_t noff = (1 - bf) * STAGE + (sA - sb);
            uint32_t h0 = cvt2bf(x0.y, x0.x), h1 = cvt2bf(x0.w, x0.z);
            uint32_t h2 = cvt2bf(x1.y, x1.x), h3 = cvt2bf(x1.w, x1.z);
            uint32_t h4 = cvt2bf(x2.y, x2.x), h5 = cvt2bf(x2.w, x2.z);
            uint32_t h6 = cvt2bf(x3.y, x3.x), h7 = cvt2bf(x3.w, x3.z);
            *(uint4*)(smem + noff)      = make_uint4(h0, h1, h2, h3);
            *(uint4*)(smem + noff + 16) = make_uint4(h4, h5, h6, h7);
            uint32_t l0 = cvt2bf(x0.y - bfhi_f(h0), x0.x - bflo_f(h0));
            uint32_t l1 = cvt2bf(x0.w - bfhi_f(h1), x0.z - bflo_f(h1));
            uint32_t l2 = cvt2bf(x1.y - bfhi_f(h2), x1.x - bflo_f(h2));
            uint32_t l3 = cvt2bf(x1.w - bfhi_f(h3), x1.z - bflo_f(h3));
            uint32_t l4 = cvt2bf(x2.y - bfhi_f(h4), x2.x - bflo_f(h4));
            uint32_t l5 = cvt2bf(x2.w - bfhi_f(h5), x2.z - bflo_f(h5));
            uint32_t l6 = cvt2bf(x3.y - bfhi_f(h6), x3.x - bflo_f(h6));
            uint32_t l7 = cvt2bf(x3.w - bfhi_f(h7), x3.z - bflo_f(h7));
            *(uint4*)(smem + noff + OFF_AL)      = make_uint4(l0, l1, l2, l3);
            *(uint4*)(smem + noff + OFF_AL + 16) = make_uint4(l4, l5, l6, l7);
            CP_WAIT0();
        }
        __syncthreads();
    }

    // ---- epilogue ----
    float* c_s = (float*)smem;                 // 32 x 136 padded
    float* v_s = (float*)(smem + 32 * 136 * 4);
    for (int i = tid; i < 32 * 128; i += 256) {
        int b = i >> 7, n = i & 127;
        c_s[b * 136 + n] = g_c[b * HH + n0 + n];
    }
    if (tid < 128) v_s[tid] = v[n0 + tid];
    __syncthreads();

    const int g = lane >> 2, tig = lane & 3;
    #pragma unroll
    for (int mi = 0; mi < 4; mi++) {
        int lr0 = wy * 64 + mi * 16 + g;
        int lr1 = lr0 + 8;
        const float* cr0 = c_s + (lr0 & 31) * 136;
        const float* cr1 = c_s + (lr1 & 31) * 136;
        float e0 = 0.f, e1 = 0.f;
        #pragma unroll
        for (int nj = 0; nj < 4; nj++) {
            int c0 = wx * 32 + nj * 8 + tig * 2;
            float v0 = v_s[c0], v1 = v_s[c0 + 1];
            e0 += my_tanh(acc[mi][nj][0] + cr0[c0])     * v0
                + my_tanh(acc[mi][nj][1] + cr0[c0 + 1]) * v1;
            e1 += my_tanh(acc[mi][nj][2] + cr1[c0])     * v0
                + my_tanh(acc[mi][nj][3] + cr1[c0 + 1]) * v1;
        }
        e0 += __shfl_xor_sync(0xffffffffu, e0, 1);
        e0 += __shfl_xor_sync(0xffffffffu, e0, 2);
        e1 += __shfl_xor_sync(0xffffffffu, e1, 1);
        e1 += __shfl_xor_sync(0xffffffffu, e1, 2);
        if (tig == 0) {
            atomicAdd(&g_energy[m0 + lr0], e0);
            atomicAdd(&g_energy[m0 + lr1], e1);
        }
    }
}

// ---------------------------------------------------------------------------
// softmax over S per batch
// ---------------------------------------------------------------------------
__global__ void softmax_kernel(const void* __restrict__ mask) {
    const int b = blockIdx.x;
    const int kind = g_mask_kind;
    __shared__ float red[256];

    float lmax = -3.4e38f;
    for (int s = threadIdx.x; s < SS; s += 256) {
        int idx = s*BB + b;
        float e = mask_on(mask, idx, kind) ? g_energy[idx] : -1e10f;
        g_energy[idx] = e;
        lmax = fmaxf(lmax, e);
    }
    red[threadIdx.x] = lmax;
    __syncthreads();
    for (int o = 128; o > 0; o >>= 1) {
        if (threadIdx.x < o) red[threadIdx.x] = fmaxf(red[threadIdx.x], red[threadIdx.x + o]);
        __syncthreads();
    }
    const float mx = red[0];
    __syncthreads();

    float lsum = 0.f;
    for (int s = threadIdx.x; s < SS; s += 256) {
        int idx = s*BB + b;
        float e = __expf(g_energy[idx] - mx);
        g_attn[idx] = e;
        lsum += e;
    }
    red[threadIdx.x] = lsum;
    __syncthreads();
    for (int o = 128; o > 0; o >>= 1) {
        if (threadIdx.x < o) red[threadIdx.x] += red[threadIdx.x + o];
        __syncthreads();
    }
    const float inv = 1.f / red[0];
    __syncthreads();

    for (int s = threadIdx.x; s < SS; s += 256)
        g_attn[s*BB + b] *= inv;
}

// ---------------------------------------------------------------------------
// context[b,h] = sum_s attn[s,b]*hs[s,b,h]
// ---------------------------------------------------------------------------
__global__ void context_kernel(const float* __restrict__ hs,
                               float* __restrict__ out) {
    const int b = blockIdx.x;
    const int s0 = blockIdx.y * 128;
    const int h4 = threadIdx.x;
    float4 acc = make_float4(0.f, 0.f, 0.f, 0.f);
    for (int s = s0; s < s0 + 128; s++) {
        float w = g_attn[s*BB + b];
        float4 x = ((const float4*)(hs + (size_t)(s*BB + b)*HH))[h4];
        acc.x += w*x.x; acc.y += w*x.y; acc.z += w*x.z; acc.w += w*x.w;
    }
    float* o = out + b*HH + h4*4;
    atomicAdd(o+0, acc.x); atomicAdd(o+1, acc.y);
    atomicAdd(o+2, acc.z); atomicAdd(o+3, acc.w);
}

// ---------------------------------------------------------------------------
// Launch
// ---------------------------------------------------------------------------
extern "C" void kernel_launch(void* const* d_in, const int* in_sizes, int n_in,
                              void* d_out, int out_size) {
    const float* hidden = (const float*)d_in[0];
    const float* hs     = (const float*)d_in[1];
    const void*  mask   = d_in[2];
    const float* W1     = (const float*)d_in[3];
    const float* b1     = (const float*)d_in[4];
    const float* W2     = (const float*)d_in[5];
    const float* b2     = (const float*)d_in[6];
    const float* v      = (const float*)d_in[7];
    float* out = (float*)d_out;

    cudaFuncSetAttribute(energy_mma_kernel,
                         cudaFuncAttributeMaxDynamicSharedMemorySize, DSMEM_TOTAL);

    detect_mask_kernel<<<1, 256>>>((const unsigned char*)mask);
    convert_w_kernel<<<HH*HH/1024, 256>>>(W1);
    precompute_c_kernel<<<BB, 256>>>(hidden, W2, b1, b2);
    zero_energy_kernel<<<RR/256, 256>>>();
    energy_mma_kernel<<<dim3(HH/128, RR/128), 256, DSMEM_TOTAL>>>(hs, v);
    softmax_kernel<<<BB, 256>>>(mask);
    zero_out_kernel<<<(BB*HH)/256, 256>>>(out);
    context_kernel<<<dim3(BB, SS/128), 256>>>(hs, out);
}